// round 4
// baseline (speedup 1.0000x reference)
#include <cuda_runtime.h>

// PointerNet_30949534335591 — FINAL (terminal kernel, confirmed floor)
//
// Mathematical identity (exact, rel_err = 0.0 across R1-R3): the decoder
// computes logits of shape [B, 1] and argmaxes over the length-1 axis ->
// identically 0 for every batch element and step, independent of all LSTM
// state. The reference's own comment concedes it ("always 0, faithful to
// source"). The output is a constant zero [B, S] int32 tensor; the entire
// encoder/decoder LSTM stack (~110 GFLOP) is dead code w.r.t. the output.
//
// Performance model (validated over R1-R3):
//   - d_out is poisoned to 0xAA -> all 512 KB must be written per replay.
//   - 512 KB of stores = ~0.06 us of HBM time; measured ~5.07 us -> >98% is
//     fixed per-replay overhead (cudaGraphLaunch + single-node latency).
//   - Node-type ladder, measured: kernel node 5.79 us > memset node 5.06 us.
//     Memcpy-from-zero-buffer and multi-node variants modeled strictly worse.
//   - Noise band +/-0.05 us (5.056 / 5.088 on consecutive runs).
//
// Minimal correct graph: ONE memset node writing the minimum byte count.

extern "C" void kernel_launch(void* const* d_in, const int* in_sizes, int n_in,
                              void* d_out, int out_size) {
    (void)d_in; (void)in_sizes; (void)n_in;
    // Captured as a single CUDA-graph memset node: zero B*S int32 elements.
    cudaMemsetAsync(d_out, 0, (size_t)out_size * sizeof(int), 0);
}